// round 8
// baseline (speedup 1.0000x reference)
#include <cuda_runtime.h>
#include <math.h>

#define NN 100000
#define EE 1600000
#define C 64
#define OC 16

// ---------------- scratch (static device globals; no runtime allocation) ----
__device__ int   g_is64;
__device__ int   g_deg[NN];
__device__ float g_dinv[NN];
__device__ int   g_rowptr[NN + 1];
__device__ int   g_fill[NN];
__device__ int   g_bsum[256];
__device__ __align__(256) float2 g_edges[EE];   // .x = __int_as_float(src), .y = norm
__device__ __align__(256) float  g_t[NN * C];   // gemm output (pre-aggregation)
__device__ __align__(256) float  g_h[NN * C];   // layer output (post relu)

// Index i of the logical edge array (length 2*EE), robust to int32 vs int64.
// For little-endian int64 with nonnegative values < 2^31 the low word suffices.
__device__ __forceinline__ int edge_at(const int* __restrict__ ei32, int is64, int i) {
    return is64 ? ei32[2 * i] : ei32[i];
}

// ---------------- setup kernels --------------------------------------------
__global__ void k_detect(const int* __restrict__ ei32) {
    if (threadIdx.x == 0 && blockIdx.x == 0) {
        int is64 = 1;
        for (int i = 1; i < 64; i += 2)
            if (ei32[i] != 0) { is64 = 0; break; }
        g_is64 = is64;
    }
}

__global__ void k_zero_deg() {
    int i = blockIdx.x * blockDim.x + threadIdx.x;
    if (i < NN) g_deg[i] = 0;
}

__global__ void k_hist(const int* __restrict__ ei32) {
    int is64 = g_is64;
    int stride = gridDim.x * blockDim.x;
    for (int e = blockIdx.x * blockDim.x + threadIdx.x; e < EE; e += stride)
        atomicAdd(&g_deg[edge_at(ei32, is64, EE + e)], 1);   // dst row
}

// block-level exclusive scan of deg (1024 elems/block), also computes dinv
__global__ void k_scanA() {
    int tid = threadIdx.x;
    int i = blockIdx.x * 1024 + tid;
    int v = (i < NN) ? g_deg[i] : 0;
    if (i < NN) g_dinv[i] = rsqrtf((float)(v + 1));   // +1 self loop

    int lane = tid & 31, wid = tid >> 5;
    int incl = v;
#pragma unroll
    for (int o = 1; o < 32; o <<= 1) {
        int t = __shfl_up_sync(0xffffffffu, incl, o);
        if (lane >= o) incl += t;
    }
    __shared__ int wsum[32];
    if (lane == 31) wsum[wid] = incl;
    __syncthreads();
    if (wid == 0) {
        int xi = wsum[lane];
#pragma unroll
        for (int o = 1; o < 32; o <<= 1) {
            int t = __shfl_up_sync(0xffffffffu, xi, o);
            if (lane >= o) xi += t;
        }
        wsum[lane] = xi;
    }
    __syncthreads();
    int base = wid ? wsum[wid - 1] : 0;
    if (i < NN) g_rowptr[i] = base + incl - v;          // block-local exclusive
    if (tid == 1023) g_bsum[blockIdx.x] = base + incl;  // block total
}

__global__ void k_scanB() {   // 98 block sums -> exclusive, trivial serial
    if (threadIdx.x == 0 && blockIdx.x == 0) {
        int run = 0;
        for (int i = 0; i < 98; i++) { int t = g_bsum[i]; g_bsum[i] = run; run += t; }
    }
}

__global__ void k_scanC() {
    int i = blockIdx.x * blockDim.x + threadIdx.x;
    if (i < NN) {
        int r = g_rowptr[i] + g_bsum[i >> 10];
        g_rowptr[i] = r;
        g_fill[i]   = r;
    }
    if (i == 0) g_rowptr[NN] = EE;
}

__global__ void k_scatter(const int* __restrict__ ei32) {
    int is64 = g_is64;
    int stride = gridDim.x * blockDim.x;
    for (int e = blockIdx.x * blockDim.x + threadIdx.x; e < EE; e += stride) {
        int s = edge_at(ei32, is64, e);
        int d = edge_at(ei32, is64, EE + e);
        int pos = atomicAdd(&g_fill[d], 1);
        g_edges[pos] = make_float2(__int_as_float(s), g_dinv[s] * g_dinv[d]);
    }
}

// ---------------- 64x64 GEMM: g_t[N,64] = X[N,64] @ W[64,64] ---------------
// 64 rows/block, 64 threads, 8x8 register tile per thread.
// X == nullptr means "read g_h" (layer 2 input).
__global__ void k_gemm64(const float* __restrict__ X, const float* __restrict__ W) {
    __shared__ float xs[64][65];   // pad 65: ty-stride hits distinct banks
    __shared__ float ws[64][64];
    int tid = threadIdx.x;
    int row0 = blockIdx.x * 64;
    const float* Xp = X ? X : g_h;

    const float4* W4 = (const float4*)W;
    float4* ws4 = (float4*)&ws[0][0];
    for (int j = tid; j < 1024; j += 64) ws4[j] = W4[j];

    for (int j = tid; j < 1024; j += 64) {
        int r = j >> 4, k4 = j & 15;
        int gr = row0 + r;
        float4 v = (gr < NN) ? ((const float4*)Xp)[gr * 16 + k4]
                             : make_float4(0.f, 0.f, 0.f, 0.f);
        xs[r][k4 * 4 + 0] = v.x; xs[r][k4 * 4 + 1] = v.y;
        xs[r][k4 * 4 + 2] = v.z; xs[r][k4 * 4 + 3] = v.w;
    }
    __syncthreads();

    int tx = tid & 7, ty = tid >> 3;
    float acc[8][8];
#pragma unroll
    for (int i = 0; i < 8; i++)
#pragma unroll
        for (int j = 0; j < 8; j++) acc[i][j] = 0.f;

#pragma unroll 8
    for (int k = 0; k < 64; k++) {
        float a[8];
#pragma unroll
        for (int i = 0; i < 8; i++) a[i] = xs[ty * 8 + i][k];
        float4 b0 = *(const float4*)&ws[k][tx * 8];
        float4 b1 = *(const float4*)&ws[k][tx * 8 + 4];
        float b[8] = {b0.x, b0.y, b0.z, b0.w, b1.x, b1.y, b1.z, b1.w};
#pragma unroll
        for (int i = 0; i < 8; i++)
#pragma unroll
            for (int j = 0; j < 8; j++) acc[i][j] = fmaf(a[i], b[j], acc[i][j]);
    }

#pragma unroll
    for (int i = 0; i < 8; i++) {
        int gr = row0 + ty * 8 + i;
        if (gr < NN) {
            float4 o0 = {acc[i][0], acc[i][1], acc[i][2], acc[i][3]};
            float4 o1 = {acc[i][4], acc[i][5], acc[i][6], acc[i][7]};
            ((float4*)g_t)[gr * 16 + tx * 2 + 0] = o0;
            ((float4*)g_t)[gr * 16 + tx * 2 + 1] = o1;
        }
    }
}

// ---------------- aggregation: warp per node, CSR gather-reduce ------------
// reads g_t, writes relu(agg + bias) into g_h
__global__ void k_agg(const float* __restrict__ bias) {
    int n    = (blockIdx.x * blockDim.x + threadIdx.x) >> 5;
    int lane = threadIdx.x & 31;
    if (n >= NN) return;
    const float2* T2 = (const float2*)g_t;

    float di = g_dinv[n];
    float ws = di * di;                 // self-loop weight
    float2 sv = T2[n * 32 + lane];
    float a0 = sv.x * ws, a1 = sv.y * ws;

    int j = g_rowptr[n], end = g_rowptr[n + 1];
    for (; j + 4 <= end; j += 4) {
        float2 e0 = g_edges[j + 0], e1 = g_edges[j + 1];
        float2 e2 = g_edges[j + 2], e3 = g_edges[j + 3];
        float2 v0 = T2[__float_as_int(e0.x) * 32 + lane];
        float2 v1 = T2[__float_as_int(e1.x) * 32 + lane];
        float2 v2 = T2[__float_as_int(e2.x) * 32 + lane];
        float2 v3 = T2[__float_as_int(e3.x) * 32 + lane];
        a0 = fmaf(v0.x, e0.y, a0); a1 = fmaf(v0.y, e0.y, a1);
        a0 = fmaf(v1.x, e1.y, a0); a1 = fmaf(v1.y, e1.y, a1);
        a0 = fmaf(v2.x, e2.y, a0); a1 = fmaf(v2.y, e2.y, a1);
        a0 = fmaf(v3.x, e3.y, a0); a1 = fmaf(v3.y, e3.y, a1);
    }
    for (; j < end; j++) {
        float2 e = g_edges[j];
        float2 v = T2[__float_as_int(e.x) * 32 + lane];
        a0 = fmaf(v.x, e.y, a0); a1 = fmaf(v.y, e.y, a1);
    }

    float b0 = bias[2 * lane], b1 = bias[2 * lane + 1];
    a0 = fmaxf(a0 + b0, 0.f);
    a1 = fmaxf(a1 + b1, 0.f);
    ((float2*)g_h)[n * 32 + lane] = make_float2(a0, a1);
}

// ---------------- FC (64->16) + log_softmax, warp per node -----------------
__global__ void k_fc(const float* __restrict__ Wfc, const float* __restrict__ bfc,
                     float* __restrict__ out) {
    int n    = (blockIdx.x * blockDim.x + threadIdx.x) >> 5;
    int lane = threadIdx.x & 31;
    if (n >= NN) return;

    float2 h = ((const float2*)g_h)[n * 32 + lane];   // channels 2*lane, 2*lane+1
    const float4* W4 = (const float4*)Wfc;            // [64][16] row-major

    float p[16];
#pragma unroll
    for (int q = 0; q < 4; q++) {
        float4 w0 = W4[(2 * lane) * 4 + q];
        float4 w1 = W4[(2 * lane + 1) * 4 + q];
        p[4 * q + 0] = h.x * w0.x + h.y * w1.x;
        p[4 * q + 1] = h.x * w0.y + h.y * w1.y;
        p[4 * q + 2] = h.x * w0.z + h.y * w1.z;
        p[4 * q + 3] = h.x * w0.w + h.y * w1.w;
    }
#pragma unroll
    for (int off = 16; off >= 1; off >>= 1)
#pragma unroll
        for (int c = 0; c < 16; c++)
            p[c] += __shfl_xor_sync(0xffffffffu, p[c], off);

    float m = -3.4e38f;
#pragma unroll
    for (int c = 0; c < 16; c++) { p[c] += bfc[c]; m = fmaxf(m, p[c]); }
    float sum = 0.f;
#pragma unroll
    for (int c = 0; c < 16; c++) sum += expf(p[c] - m);
    float lse = m + logf(sum);

    float val = 0.f;
#pragma unroll
    for (int c = 0; c < 16; c++) if (lane == c) val = p[c];
    if (lane < 16) out[n * 16 + lane] = val - lse;
}

// ---------------- launch ----------------------------------------------------
extern "C" void kernel_launch(void* const* d_in, const int* in_sizes, int n_in,
                              void* d_out, int out_size) {
    const float* x    = (const float*)d_in[0];
    const int*   ei32 = (const int*)d_in[1];   // int32 or int64 — detected on device
    const float* W1   = (const float*)d_in[2];
    const float* b1   = (const float*)d_in[3];
    const float* W2   = (const float*)d_in[4];
    const float* b2   = (const float*)d_in[5];
    const float* Wfc  = (const float*)d_in[6];
    const float* bfc  = (const float*)d_in[7];
    float*       out  = (float*)d_out;

    k_detect<<<1, 32>>>(ei32);
    k_zero_deg<<<(NN + 255) / 256, 256>>>();
    k_hist<<<1024, 256>>>(ei32);
    k_scanA<<<(NN + 1023) / 1024, 1024>>>();
    k_scanB<<<1, 32>>>();
    k_scanC<<<(NN + 255) / 256, 256>>>();
    k_scatter<<<1024, 256>>>(ei32);

    k_gemm64<<<(NN + 63) / 64, 64>>>(x, W1);
    k_agg<<<(NN + 7) / 8, 256>>>(b1);
    k_gemm64<<<(NN + 63) / 64, 64>>>(nullptr, W2);
    k_agg<<<(NN + 7) / 8, 256>>>(b2);
    k_fc<<<(NN + 7) / 8, 256>>>(Wfc, bfc, out);
}

// round 10
// speedup vs baseline: 1.0454x; 1.0454x over previous
#include <cuda_runtime.h>
#include <cuda_fp16.h>
#include <math.h>

#define NN 100000
#define EE 1600000
#define C 64
#define OC 16

// ---------------- scratch (static device globals; no runtime allocation) ----
__device__ int   g_is64;
__device__ int   g_deg[NN];
__device__ float g_dinv[NN];
__device__ int   g_rowptr[NN + 1];
__device__ int   g_fill[NN];
__device__ int   g_bsum[256];
__device__ __align__(256) float2  g_edges[EE];    // .x = __int_as_float(src), .y = norm
__device__ __align__(256) __half2 g_t16[NN * 32]; // gemm output, fp16 (gathered buffer)
__device__ __align__(256) float   g_h[NN * C];    // layer-1 output (post relu), fp32

// Index i of the logical edge array (length 2*EE), robust to int32 vs int64.
__device__ __forceinline__ int edge_at(const int* __restrict__ ei32, int is64, int i) {
    return is64 ? ei32[2 * i] : ei32[i];
}

// ---------------- setup kernels --------------------------------------------
// zero degree array + dtype detection (thread 0)
__global__ void k_init(const int* __restrict__ ei32) {
    int i = blockIdx.x * blockDim.x + threadIdx.x;
    if (i < NN) g_deg[i] = 0;
    if (i == 0) {
        int is64 = 1;
        for (int k = 1; k < 64; k += 2)
            if (ei32[k] != 0) { is64 = 0; break; }
        g_is64 = is64;
    }
}

__global__ void k_hist(const int* __restrict__ ei32) {
    int is64 = g_is64;
    int idx = blockIdx.x * blockDim.x + threadIdx.x;
    int stride = gridDim.x * blockDim.x;
    if (!is64) {
        const int4* pd = (const int4*)(ei32 + EE);
        for (int e4 = idx; e4 < EE / 4; e4 += stride) {
            int4 d = __ldg(&pd[e4]);
            atomicAdd(&g_deg[d.x], 1); atomicAdd(&g_deg[d.y], 1);
            atomicAdd(&g_deg[d.z], 1); atomicAdd(&g_deg[d.w], 1);
        }
    } else {
        for (int e = idx; e < EE; e += stride)
            atomicAdd(&g_deg[edge_at(ei32, 1, EE + e)], 1);
    }
}

// block-level exclusive scan of deg (1024 elems/block), also computes dinv
__global__ void k_scanA() {
    int tid = threadIdx.x;
    int i = blockIdx.x * 1024 + tid;
    int v = (i < NN) ? g_deg[i] : 0;
    if (i < NN) g_dinv[i] = rsqrtf((float)(v + 1));   // +1 self loop

    int lane = tid & 31, wid = tid >> 5;
    int incl = v;
#pragma unroll
    for (int o = 1; o < 32; o <<= 1) {
        int t = __shfl_up_sync(0xffffffffu, incl, o);
        if (lane >= o) incl += t;
    }
    __shared__ int wsum[32];
    if (lane == 31) wsum[wid] = incl;
    __syncthreads();
    if (wid == 0) {
        int xi = wsum[lane];
#pragma unroll
        for (int o = 1; o < 32; o <<= 1) {
            int t = __shfl_up_sync(0xffffffffu, xi, o);
            if (lane >= o) xi += t;
        }
        wsum[lane] = xi;
    }
    __syncthreads();
    int base = wid ? wsum[wid - 1] : 0;
    if (i < NN) g_rowptr[i] = base + incl - v;          // block-local exclusive
    if (tid == 1023) g_bsum[blockIdx.x] = base + incl;  // block total
}

__global__ void k_scanB() {   // 98 block sums -> exclusive
    if (threadIdx.x == 0 && blockIdx.x == 0) {
        int run = 0;
        for (int i = 0; i < 98; i++) { int t = g_bsum[i]; g_bsum[i] = run; run += t; }
    }
}

__global__ void k_scanC() {
    int i = blockIdx.x * blockDim.x + threadIdx.x;
    if (i < NN) {
        int r = g_rowptr[i] + g_bsum[i >> 10];
        g_rowptr[i] = r;
        g_fill[i]   = r;
    }
    if (i == 0) g_rowptr[NN] = EE;
}

__global__ void k_scatter(const int* __restrict__ ei32) {
    int is64 = g_is64;
    int idx = blockIdx.x * blockDim.x + threadIdx.x;
    int stride = gridDim.x * blockDim.x;
    if (!is64) {
        const int4* ps = (const int4*)ei32;
        const int4* pd = (const int4*)(ei32 + EE);
        for (int e4 = idx; e4 < EE / 4; e4 += stride) {
            int4 s = __ldg(&ps[e4]);
            int4 d = __ldg(&pd[e4]);
            int sa[4] = {s.x, s.y, s.z, s.w};
            int da[4] = {d.x, d.y, d.z, d.w};
#pragma unroll
            for (int q = 0; q < 4; q++) {
                int pos = atomicAdd(&g_fill[da[q]], 1);
                g_edges[pos] = make_float2(__int_as_float(sa[q]),
                                           g_dinv[sa[q]] * g_dinv[da[q]]);
            }
        }
    } else {
        for (int e = idx; e < EE; e += stride) {
            int s = edge_at(ei32, 1, e);
            int d = edge_at(ei32, 1, EE + e);
            int pos = atomicAdd(&g_fill[d], 1);
            g_edges[pos] = make_float2(__int_as_float(s), g_dinv[s] * g_dinv[d]);
        }
    }
}

// ---------------- 64x64 GEMM: g_t16[N,64] = X[N,64] @ W[64,64] (fp16 out) --
// 64 rows/block, 64 threads, 8x8 register tile per thread.
// X == nullptr means "read g_h" (layer 2 input).
__global__ void k_gemm64(const float* __restrict__ X, const float* __restrict__ W) {
    __shared__ float xs[64][65];
    __shared__ float ws[64][64];
    int tid = threadIdx.x;
    int row0 = blockIdx.x * 64;
    const float* Xp = X ? X : g_h;

    const float4* W4 = (const float4*)W;
    float4* ws4 = (float4*)&ws[0][0];
    for (int j = tid; j < 1024; j += 64) ws4[j] = __ldg(&W4[j]);

    for (int j = tid; j < 1024; j += 64) {
        int r = j >> 4, k4 = j & 15;
        int gr = row0 + r;
        float4 v = (gr < NN) ? __ldg(&((const float4*)Xp)[gr * 16 + k4])
                             : make_float4(0.f, 0.f, 0.f, 0.f);
        xs[r][k4 * 4 + 0] = v.x; xs[r][k4 * 4 + 1] = v.y;
        xs[r][k4 * 4 + 2] = v.z; xs[r][k4 * 4 + 3] = v.w;
    }
    __syncthreads();

    int tx = tid & 7, ty = tid >> 3;
    float acc[8][8];
#pragma unroll
    for (int i = 0; i < 8; i++)
#pragma unroll
        for (int j = 0; j < 8; j++) acc[i][j] = 0.f;

#pragma unroll 8
    for (int k = 0; k < 64; k++) {
        float a[8];
#pragma unroll
        for (int i = 0; i < 8; i++) a[i] = xs[ty * 8 + i][k];
        float4 b0 = *(const float4*)&ws[k][tx * 8];
        float4 b1 = *(const float4*)&ws[k][tx * 8 + 4];
        float b[8] = {b0.x, b0.y, b0.z, b0.w, b1.x, b1.y, b1.z, b1.w};
#pragma unroll
        for (int i = 0; i < 8; i++)
#pragma unroll
            for (int j = 0; j < 8; j++) acc[i][j] = fmaf(a[i], b[j], acc[i][j]);
    }

    // convert to fp16 and store: thread covers cols [tx*8, tx*8+8) = 4 half2 = 16B
#pragma unroll
    for (int i = 0; i < 8; i++) {
        int gr = row0 + ty * 8 + i;
        if (gr < NN) {
            union { __half2 h[4]; uint4 u; } pk;
#pragma unroll
            for (int q = 0; q < 4; q++)
                pk.h[q] = __floats2half2_rn(acc[i][2 * q], acc[i][2 * q + 1]);
            ((uint4*)g_t16)[gr * 8 + tx] = pk.u;
        }
    }
}

// ---------------- aggregation: warp per node, CSR gather-reduce ------------
// reads g_t16 (fp16), accumulates fp32. FC=0: relu+bias -> g_h.
// FC=1: relu+bias -> fused FC(64->16) + log_softmax -> out.
template <int FC>
__global__ void k_agg(const float* __restrict__ bias,
                      const float* __restrict__ Wfc,
                      const float* __restrict__ bfc,
                      float* __restrict__ out) {
    int n    = (blockIdx.x * blockDim.x + threadIdx.x) >> 5;
    int lane = threadIdx.x & 31;
    if (n >= NN) return;
    const __half2* T16 = (const __half2*)g_t16;

    float di = g_dinv[n];
    float ws = di * di;
    float2 sv = __half22float2(__ldg(&T16[n * 32 + lane]));
    float a0 = sv.x * ws, a1 = sv.y * ws;

    int j = g_rowptr[n], end = g_rowptr[n + 1];
    for (; j + 4 <= end; j += 4) {
        float2 e0 = g_edges[j + 0], e1 = g_edges[j + 1];
        float2 e2 = g_edges[j + 2], e3 = g_edges[j + 3];
        float2 v0 = __half22float2(__ldg(&T16[__float_as_int(e0.x) * 32 + lane]));
        float2 v1 = __half22float2(__ldg(&T16[__float_as_int(e1.x) * 32 + lane]));
        float2 v2 = __half22float2(__ldg(&T16[__float_as_int(e2.x) * 32 + lane]));
        float2 v3 = __half22float2(__ldg(&T16[__float_as_int(e3.x) * 32 + lane]));
        a0 = fmaf(v0.x, e0.y, a0); a1 = fmaf(v0.y, e0.y, a1);
        a0 = fmaf(v1.x, e1.y, a0); a1 = fmaf(v1.y, e1.y, a1);
        a0 = fmaf(v2.x, e2.y, a0); a1 = fmaf(v2.y, e2.y, a1);
        a0 = fmaf(v3.x, e3.y, a0); a1 = fmaf(v3.y, e3.y, a1);
    }
    for (; j < end; j++) {
        float2 e = g_edges[j];
        float2 v = __half22float2(__ldg(&T16[__float_as_int(e.x) * 32 + lane]));
        a0 = fmaf(v.x, e.y, a0); a1 = fmaf(v.y, e.y, a1);
    }

    float2 b = ((const float2*)bias)[lane];
    a0 = fmaxf(a0 + b.x, 0.f);
    a1 = fmaxf(a1 + b.y, 0.f);

    if (FC == 0) {
        ((float2*)g_h)[n * 32 + lane] = make_float2(a0, a1);
    } else {
        // fused FC: channels (2*lane, 2*lane+1) x Wfc[64][16]
        const float4* W4 = (const float4*)Wfc;
        float p[16];
#pragma unroll
        for (int q = 0; q < 4; q++) {
            float4 w0 = __ldg(&W4[(2 * lane) * 4 + q]);
            float4 w1 = __ldg(&W4[(2 * lane + 1) * 4 + q]);
            p[4 * q + 0] = a0 * w0.x + a1 * w1.x;
            p[4 * q + 1] = a0 * w0.y + a1 * w1.y;
            p[4 * q + 2] = a0 * w0.z + a1 * w1.z;
            p[4 * q + 3] = a0 * w0.w + a1 * w1.w;
        }
#pragma unroll
        for (int off = 16; off >= 1; off >>= 1)
#pragma unroll
            for (int c = 0; c < 16; c++)
                p[c] += __shfl_xor_sync(0xffffffffu, p[c], off);

        float m = -3.4e38f;
#pragma unroll
        for (int c = 0; c < 16; c++) { p[c] += bfc[c]; m = fmaxf(m, p[c]); }
        float sum = 0.f;
#pragma unroll
        for (int c = 0; c < 16; c++) sum += expf(p[c] - m);
        float lse = m + logf(sum);

        float val = 0.f;
#pragma unroll
        for (int c = 0; c < 16; c++) if (lane == c) val = p[c];
        if (lane < 16) out[n * 16 + lane] = val - lse;
    }
}

// ---------------- launch ----------------------------------------------------
extern "C" void kernel_launch(void* const* d_in, const int* in_sizes, int n_in,
                              void* d_out, int out_size) {
    const float* x    = (const float*)d_in[0];
    const int*   ei32 = (const int*)d_in[1];   // int32 or int64 — detected on device
    const float* W1   = (const float*)d_in[2];
    const float* b1   = (const float*)d_in[3];
    const float* W2   = (const float*)d_in[4];
    const float* b2   = (const float*)d_in[5];
    const float* Wfc  = (const float*)d_in[6];
    const float* bfc  = (const float*)d_in[7];
    float*       out  = (float*)d_out;

    k_init<<<(NN + 255) / 256, 256>>>(ei32);
    k_hist<<<1024, 256>>>(ei32);
    k_scanA<<<(NN + 1023) / 1024, 1024>>>();
    k_scanB<<<1, 32>>>();
    k_scanC<<<(NN + 255) / 256, 256>>>();
    k_scatter<<<1024, 256>>>(ei32);           // launch #5 -> ncu capture target

    k_gemm64<<<(NN + 63) / 64, 64>>>(x, W1);
    k_agg<0><<<(NN + 7) / 8, 256>>>(b1, nullptr, nullptr, nullptr);
    k_gemm64<<<(NN + 63) / 64, 64>>>(nullptr, W2);
    k_agg<1><<<(NN + 7) / 8, 256>>>(b2, Wfc, bfc, out);
}

// round 11
// speedup vs baseline: 1.2215x; 1.1684x over previous
#include <cuda_runtime.h>
#include <cuda_fp16.h>
#include <math.h>

#define NN 100000
#define EE 1600000
#define C 64
#define OC 16

// ---------------- scratch (static device globals; no runtime allocation) ----
// INVARIANT: g_deg is all-zero at every kernel_launch entry (zero-init at load,
// k_scanA resets it after consuming). Deterministic: identical work every call.
__device__ int   g_deg[NN];
__device__ float g_dinv[NN];
__device__ int   g_rowptr[NN + 1];
__device__ int   g_fill[NN];
__device__ int   g_bsum[128];
__device__ __align__(256) float2  g_edges[EE];    // .x = __int_as_float(src), .y = norm
__device__ __align__(256) __half2 g_t16[NN * 32]; // gemm output, fp16 (gathered buffer)
__device__ __align__(256) float   g_h[NN * C];    // layer-1 output (post relu), fp32

// Per-block int32/int64 self-detection: for little-endian int64 with values
// < 2^31 every odd 32-bit word is zero; for random int32 in [0,1e5) the odds
// all 32 are zero is ~1e-160.
__device__ __forceinline__ int detect_is64(const int* __restrict__ ei32, int tid) {
    __shared__ int s_is64;
    if (tid < 32) {
        int w = __ldg(&ei32[2 * tid + 1]);
        int all0 = __all_sync(0xffffffffu, w == 0);
        if (tid == 0) s_is64 = all0;
    }
    __syncthreads();
    return s_is64;
}

// ---------------- setup kernels --------------------------------------------
__global__ void k_hist(const int* __restrict__ ei32) {
    int tid = threadIdx.x;
    int is64 = detect_is64(ei32, tid);
    int idx = blockIdx.x * blockDim.x + tid;
    int stride = gridDim.x * blockDim.x;
    if (!is64) {
        const int4* pd = (const int4*)(ei32 + EE);
        for (int e4 = idx; e4 < EE / 4; e4 += stride) {
            int4 d = __ldg(&pd[e4]);
            atomicAdd(&g_deg[d.x], 1); atomicAdd(&g_deg[d.y], 1);
            atomicAdd(&g_deg[d.z], 1); atomicAdd(&g_deg[d.w], 1);
        }
    } else {
        const int4* pd = (const int4*)(ei32 + 2 * EE);   // int64 dst row
        for (int e2 = idx; e2 < EE / 2; e2 += stride) {  // 2 edges per int4
            int4 d = __ldg(&pd[e2]);
            atomicAdd(&g_deg[d.x], 1); atomicAdd(&g_deg[d.z], 1);
        }
    }
}

// block-level scan of deg (1024 elems/block): writes block-local exclusive
// prefix to g_rowptr, block total to g_bsum, dinv, and resets g_deg to 0.
__global__ void k_scanA() {
    int tid = threadIdx.x;
    int i = blockIdx.x * 1024 + tid;
    int v = 0;
    if (i < NN) {
        v = g_deg[i];
        g_deg[i] = 0;                                  // restore zero-invariant
        g_dinv[i] = rsqrtf((float)(v + 1));            // +1 self loop
    }

    int lane = tid & 31, wid = tid >> 5;
    int incl = v;
#pragma unroll
    for (int o = 1; o < 32; o <<= 1) {
        int t = __shfl_up_sync(0xffffffffu, incl, o);
        if (lane >= o) incl += t;
    }
    __shared__ int wsum[32];
    if (lane == 31) wsum[wid] = incl;
    __syncthreads();
    if (wid == 0) {
        int xi = wsum[lane];
#pragma unroll
        for (int o = 1; o < 32; o <<= 1) {
            int t = __shfl_up_sync(0xffffffffu, xi, o);
            if (lane >= o) xi += t;
        }
        wsum[lane] = xi;
    }
    __syncthreads();
    int base = wid ? wsum[wid - 1] : 0;
    if (i < NN) g_rowptr[i] = base + incl - v;          // block-local exclusive
    if (tid == 1023) g_bsum[blockIdx.x] = base + incl;  // block TOTAL
}

// adds global prefix: each 256-thread block lies inside one 1024-group g,
// prefix = sum of g_bsum[0..g-1] computed by block-local reduction (<=97 vals).
__global__ void k_scanC() {
    int tid = threadIdx.x;
    int g = blockIdx.x >> 2;                  // 1024-group of this block
    int v = (tid < g) ? g_bsum[tid] : 0;      // g <= 97 < 256
#pragma unroll
    for (int o = 16; o >= 1; o >>= 1) v += __shfl_xor_sync(0xffffffffu, v, o);
    __shared__ int wred[8];
    if ((tid & 31) == 0) wred[tid >> 5] = v;
    __syncthreads();
    __shared__ int s_pref;
    if (tid == 0) {
        int p = 0;
#pragma unroll
        for (int w = 0; w < 8; w++) p += wred[w];
        s_pref = p;
    }
    __syncthreads();
    int pref = s_pref;

    int i = blockIdx.x * 256 + tid;
    if (i < NN) {
        int r = g_rowptr[i] + pref;
        g_rowptr[i] = r;
        g_fill[i]   = r;
    }
    if (i == 0) g_rowptr[NN] = EE;
}

__global__ void k_scatter(const int* __restrict__ ei32) {
    int tid = threadIdx.x;
    int is64 = detect_is64(ei32, tid);
    int idx = blockIdx.x * blockDim.x + tid;
    int stride = gridDim.x * blockDim.x;
    if (!is64) {
        const int4* ps = (const int4*)ei32;
        const int4* pd = (const int4*)(ei32 + EE);
        for (int e4 = idx; e4 < EE / 4; e4 += stride) {
            int4 s = __ldg(&ps[e4]);
            int4 d = __ldg(&pd[e4]);
            int sa[4] = {s.x, s.y, s.z, s.w};
            int da[4] = {d.x, d.y, d.z, d.w};
#pragma unroll
            for (int q = 0; q < 4; q++) {
                int pos = atomicAdd(&g_fill[da[q]], 1);
                g_edges[pos] = make_float2(__int_as_float(sa[q]),
                                           g_dinv[sa[q]] * g_dinv[da[q]]);
            }
        }
    } else {
        const long long* es = (const long long*)ei32;
        for (int e = idx; e < EE; e += stride) {
            int s = (int)__ldg(&es[e]);
            int d = (int)__ldg(&es[EE + e]);
            int pos = atomicAdd(&g_fill[d], 1);
            g_edges[pos] = make_float2(__int_as_float(s), g_dinv[s] * g_dinv[d]);
        }
    }
}

// ---------------- GEMM: g_t16[N,64] = X[N,64] @ W[64,64] (fp16 out) --------
// 128 rows x 64 cols per block, 256 threads, 8x4 register tile per thread.
// X == nullptr means "read g_h" (layer 2 input).
__global__ __launch_bounds__(256) void k_gemm64(const float* __restrict__ X,
                                                const float* __restrict__ W) {
    __shared__ float xs[128][65];   // 33.3 KB (pad 65: conflict-free column reads)
    __shared__ float ws[64][64];    // 16.4 KB
    int tid = threadIdx.x;
    int row0 = blockIdx.x * 128;
    const float* Xp = X ? X : g_h;

    const float4* W4 = (const float4*)W;
    float4* ws4 = (float4*)&ws[0][0];
#pragma unroll
    for (int q = 0; q < 4; q++) ws4[tid + q * 256] = __ldg(&W4[tid + q * 256]);

#pragma unroll
    for (int q = 0; q < 8; q++) {
        int j = tid + q * 256;              // 0..2047
        int r = j >> 4, k4 = j & 15;
        int gr = row0 + r;
        float4 v = (gr < NN) ? __ldg(&((const float4*)Xp)[gr * 16 + k4])
                             : make_float4(0.f, 0.f, 0.f, 0.f);
        xs[r][k4 * 4 + 0] = v.x; xs[r][k4 * 4 + 1] = v.y;
        xs[r][k4 * 4 + 2] = v.z; xs[r][k4 * 4 + 3] = v.w;
    }
    __syncthreads();

    int tx = tid & 15, ty = tid >> 4;       // tx: 16 col-tiles, ty: 16 row-tiles
    float acc[8][4];
#pragma unroll
    for (int i = 0; i < 8; i++)
#pragma unroll
        for (int j = 0; j < 4; j++) acc[i][j] = 0.f;

#pragma unroll 8
    for (int k = 0; k < 64; k++) {
        float a[8];
#pragma unroll
        for (int i = 0; i < 8; i++) a[i] = xs[ty * 8 + i][k];
        float4 b = *(const float4*)&ws[k][tx * 4];
#pragma unroll
        for (int i = 0; i < 8; i++) {
            acc[i][0] = fmaf(a[i], b.x, acc[i][0]);
            acc[i][1] = fmaf(a[i], b.y, acc[i][1]);
            acc[i][2] = fmaf(a[i], b.z, acc[i][2]);
            acc[i][3] = fmaf(a[i], b.w, acc[i][3]);
        }
    }

    // cols tx*4..tx*4+3 = 2 half2 = one uint2 per row
#pragma unroll
    for (int i = 0; i < 8; i++) {
        int gr = row0 + ty * 8 + i;
        if (gr < NN) {
            union { __half2 h[2]; uint2 u; } pk;
            pk.h[0] = __floats2half2_rn(acc[i][0], acc[i][1]);
            pk.h[1] = __floats2half2_rn(acc[i][2], acc[i][3]);
            ((uint2*)g_t16)[gr * 16 + tx] = pk.u;
        }
    }
}

// ---------------- aggregation: warp per node, CSR gather-reduce ------------
// reads g_t16 (fp16), accumulates fp32. FC=0: relu+bias -> g_h.
// FC=1: relu+bias -> fused FC(64->16) + log_softmax -> out.
template <int FC>
__global__ void k_agg(const float* __restrict__ bias,
                      const float* __restrict__ Wfc,
                      const float* __restrict__ bfc,
                      float* __restrict__ out) {
    int n    = (blockIdx.x * blockDim.x + threadIdx.x) >> 5;
    int lane = threadIdx.x & 31;
    if (n >= NN) return;
    const __half2* T16 = (const __half2*)g_t16;

    float di = g_dinv[n];
    float ws = di * di;
    float2 sv = __half22float2(__ldg(&T16[n * 32 + lane]));
    float a0 = sv.x * ws, a1 = sv.y * ws;

    int j = g_rowptr[n], end = g_rowptr[n + 1];
    for (; j + 8 <= end; j += 8) {
        float2 e[8];
#pragma unroll
        for (int q = 0; q < 8; q++) e[q] = __ldg(&g_edges[j + q]);
        float2 v[8];
#pragma unroll
        for (int q = 0; q < 8; q++)
            v[q] = __half22float2(__ldg(&T16[__float_as_int(e[q].x) * 32 + lane]));
#pragma unroll
        for (int q = 0; q < 8; q++) {
            a0 = fmaf(v[q].x, e[q].y, a0);
            a1 = fmaf(v[q].y, e[q].y, a1);
        }
    }
    for (; j < end; j++) {
        float2 e = __ldg(&g_edges[j]);
        float2 v = __half22float2(__ldg(&T16[__float_as_int(e.x) * 32 + lane]));
        a0 = fmaf(v.x, e.y, a0); a1 = fmaf(v.y, e.y, a1);
    }

    float2 b = __ldg(&((const float2*)bias)[lane]);
    a0 = fmaxf(a0 + b.x, 0.f);
    a1 = fmaxf(a1 + b.y, 0.f);

    if (FC == 0) {
        ((float2*)g_h)[n * 32 + lane] = make_float2(a0, a1);
    } else {
        // fused FC: channels (2*lane, 2*lane+1) x Wfc[64][16]
        const float4* W4 = (const float4*)Wfc;
        float p[16];
#pragma unroll
        for (int q = 0; q < 4; q++) {
            float4 w0 = __ldg(&W4[(2 * lane) * 4 + q]);
            float4 w1 = __ldg(&W4[(2 * lane + 1) * 4 + q]);
            p[4 * q + 0] = a0 * w0.x + a1 * w1.x;
            p[4 * q + 1] = a0 * w0.y + a1 * w1.y;
            p[4 * q + 2] = a0 * w0.z + a1 * w1.z;
            p[4 * q + 3] = a0 * w0.w + a1 * w1.w;
        }
#pragma unroll
        for (int off = 16; off >= 1; off >>= 1)
#pragma unroll
            for (int c = 0; c < 16; c++)
                p[c] += __shfl_xor_sync(0xffffffffu, p[c], off);

        float m = -3.4e38f;
#pragma unroll
        for (int c = 0; c < 16; c++) { p[c] += __ldg(&bfc[c]); m = fmaxf(m, p[c]); }

        // select p[lane] (lane<16), single expf per lane, 16-lane shfl reduce
        float val = 0.f;
#pragma unroll
        for (int c = 0; c < 16; c++) if (lane == c) val = p[c];
        float ex = (lane < 16) ? expf(val - m) : 0.f;
#pragma unroll
        for (int off = 8; off >= 1; off >>= 1)
            ex += __shfl_xor_sync(0xffffffffu, ex, off);
        float lse = m + logf(ex);

        if (lane < 16) out[n * 16 + lane] = val - lse;
    }
}

// ---------------- launch ----------------------------------------------------
extern "C" void kernel_launch(void* const* d_in, const int* in_sizes, int n_in,
                              void* d_out, int out_size) {
    const float* x    = (const float*)d_in[0];
    const int*   ei32 = (const int*)d_in[1];   // int32 or int64 — detected on device
    const float* W1   = (const float*)d_in[2];
    const float* b1   = (const float*)d_in[3];
    const float* W2   = (const float*)d_in[4];
    const float* b2   = (const float*)d_in[5];
    const float* Wfc  = (const float*)d_in[6];
    const float* bfc  = (const float*)d_in[7];
    float*       out  = (float*)d_out;

    k_hist<<<1024, 256>>>(ei32);
    k_scanA<<<(NN + 1023) / 1024, 1024>>>();
    k_scanC<<<(NN + 255) / 256, 256>>>();
    k_scatter<<<1024, 256>>>(ei32);

    k_gemm64<<<(NN + 127) / 128, 256>>>(x, W1);
    k_agg<0><<<(NN + 7) / 8, 256>>>(b1, nullptr, nullptr, nullptr);
    k_gemm64<<<(NN + 127) / 128, 256>>>(nullptr, W2);
    k_agg<1><<<(NN + 7) / 8, 256>>>(b2, Wfc, bfc, out);
}

// round 14
// speedup vs baseline: 1.2728x; 1.0420x over previous
#include <cuda_runtime.h>
#include <cuda_fp16.h>
#include <math.h>

#define NN 100000
#define EE 1600000
#define C 64
#define OC 16

// ---------------- scratch (static device globals; no runtime allocation) ----
// INVARIANT: g_deg is all-zero at every kernel_launch entry (zero-init at load,
// k_scanA resets it after consuming). Deterministic: identical work every call.
__device__ int   g_deg[NN];
__device__ float g_dinv[NN];
__device__ int   g_rowptr[NN + 1];
__device__ int   g_fill[NN];
__device__ int   g_bsum[128];
__device__ __align__(256) int     g_srcs[EE];     // CSR column indices (src node)
__device__ __align__(256) __half2 g_t16[NN * 32]; // (X@W)*dinv[row], fp16
__device__ __align__(256) float   g_h[NN * C];    // layer-1 output (post relu), fp32

// Per-block int32/int64 self-detection: for little-endian int64 with values
// < 2^31 every odd 32-bit word is zero; for random int32 in [0,1e5) the odds
// all 32 odd words are zero is ~1e-160.
__device__ __forceinline__ int detect_is64(const int* __restrict__ ei32, int tid) {
    __shared__ int s_is64;
    if (tid < 32) {
        int w = __ldg(&ei32[2 * tid + 1]);
        int all0 = __all_sync(0xffffffffu, w == 0);
        if (tid == 0) s_is64 = all0;
    }
    __syncthreads();
    return s_is64;
}

// ---------------- setup kernels --------------------------------------------
__global__ void k_hist(const int* __restrict__ ei32) {
    int tid = threadIdx.x;
    int is64 = detect_is64(ei32, tid);
    int idx = blockIdx.x * blockDim.x + tid;
    int stride = gridDim.x * blockDim.x;
    if (!is64) {
        const int4* pd = (const int4*)(ei32 + EE);
        for (int e4 = idx; e4 < EE / 4; e4 += stride) {
            int4 d = __ldg(&pd[e4]);
            atomicAdd(&g_deg[d.x], 1); atomicAdd(&g_deg[d.y], 1);
            atomicAdd(&g_deg[d.z], 1); atomicAdd(&g_deg[d.w], 1);
        }
    } else {
        const int4* pd = (const int4*)(ei32 + 2 * EE);   // int64 dst row
        for (int e2 = idx; e2 < EE / 2; e2 += stride) {  // 2 edges per int4
            int4 d = __ldg(&pd[e2]);
            atomicAdd(&g_deg[d.x], 1); atomicAdd(&g_deg[d.z], 1);
        }
    }
}

// block-level scan of deg (1024 elems/block): block-local exclusive prefix ->
// g_rowptr, block total -> g_bsum, computes dinv, resets g_deg to 0.
__global__ void k_scanA() {
    int tid = threadIdx.x;
    int i = blockIdx.x * 1024 + tid;
    int v = 0;
    if (i < NN) {
        v = g_deg[i];
        g_deg[i] = 0;                                  // restore zero-invariant
        g_dinv[i] = rsqrtf((float)(v + 1));            // +1 self loop
    }

    int lane = tid & 31, wid = tid >> 5;
    int incl = v;
#pragma unroll
    for (int o = 1; o < 32; o <<= 1) {
        int t = __shfl_up_sync(0xffffffffu, incl, o);
        if (lane >= o) incl += t;
    }
    __shared__ int wsum[32];
    if (lane == 31) wsum[wid] = incl;
    __syncthreads();
    if (wid == 0) {
        int xi = wsum[lane];
#pragma unroll
        for (int o = 1; o < 32; o <<= 1) {
            int t = __shfl_up_sync(0xffffffffu, xi, o);
            if (lane >= o) xi += t;
        }
        wsum[lane] = xi;
    }
    __syncthreads();
    int base = wid ? wsum[wid - 1] : 0;
    if (i < NN) g_rowptr[i] = base + incl - v;          // block-local exclusive
    if (tid == 1023) g_bsum[blockIdx.x] = base + incl;  // block TOTAL
}

// adds global prefix: each 256-thread block lies in one 1024-group g;
// prefix = sum of g_bsum[0..g-1] via block-local reduction (<=97 values).
__global__ void k_scanC() {
    int tid = threadIdx.x;
    int g = blockIdx.x >> 2;
    int v = (tid < g) ? g_bsum[tid] : 0;      // g <= 97 < 256
#pragma unroll
    for (int o = 16; o >= 1; o >>= 1) v += __shfl_xor_sync(0xffffffffu, v, o);
    __shared__ int wred[8];
    if ((tid & 31) == 0) wred[tid >> 5] = v;
    __syncthreads();
    __shared__ int s_pref;
    if (tid == 0) {
        int p = 0;
#pragma unroll
        for (int w = 0; w < 8; w++) p += wred[w];
        s_pref = p;
    }
    __syncthreads();
    int pref = s_pref;

    int i = blockIdx.x * 256 + tid;
    if (i < NN) {
        int r = g_rowptr[i] + pref;
        g_rowptr[i] = r;
        g_fill[i]   = r;
    }
    if (i == 0) g_rowptr[NN] = EE;
}

// scatter src index into per-dst CSR bucket (4-byte payload, no weights)
__global__ void k_scatter(const int* __restrict__ ei32) {
    int tid = threadIdx.x;
    int is64 = detect_is64(ei32, tid);
    int idx = blockIdx.x * blockDim.x + tid;
    int stride = gridDim.x * blockDim.x;
    if (!is64) {
        const int4* ps = (const int4*)ei32;
        const int4* pd = (const int4*)(ei32 + EE);
        for (int e4 = idx; e4 < EE / 4; e4 += stride) {
            int4 s = __ldg(&ps[e4]);
            int4 d = __ldg(&pd[e4]);
            int sa[4] = {s.x, s.y, s.z, s.w};
            int da[4] = {d.x, d.y, d.z, d.w};
#pragma unroll
            for (int q = 0; q < 4; q++) {
                int pos = atomicAdd(&g_fill[da[q]], 1);
                g_srcs[pos] = sa[q];
            }
        }
    } else {
        const long long* es = (const long long*)ei32;
        for (int e = idx; e < EE; e += stride) {
            int s = (int)__ldg(&es[e]);
            int d = (int)__ldg(&es[EE + e]);
            int pos = atomicAdd(&g_fill[d], 1);
            g_srcs[pos] = s;
        }
    }
}

// ---------------- GEMM: g_t16[i,:] = dinv[i] * (X[i,:] @ W) (fp16 out) -----
// 128 rows x 64 cols per block, 256 threads, 8x4 register tile per thread.
// X == nullptr means "read g_h" (layer 2 input).
__global__ __launch_bounds__(256) void k_gemm64(const float* __restrict__ X,
                                                const float* __restrict__ W) {
    __shared__ float xs[128][65];
    __shared__ float ws[64][64];
    int tid = threadIdx.x;
    int row0 = blockIdx.x * 128;
    const float* Xp = X ? X : g_h;

    const float4* W4 = (const float4*)W;
    float4* ws4 = (float4*)&ws[0][0];
#pragma unroll
    for (int q = 0; q < 4; q++) ws4[tid + q * 256] = __ldg(&W4[tid + q * 256]);

#pragma unroll
    for (int q = 0; q < 8; q++) {
        int j = tid + q * 256;              // 0..2047
        int r = j >> 4, k4 = j & 15;
        int gr = row0 + r;
        float4 v = (gr < NN) ? __ldg(&((const float4*)Xp)[gr * 16 + k4])
                             : make_float4(0.f, 0.f, 0.f, 0.f);
        xs[r][k4 * 4 + 0] = v.x; xs[r][k4 * 4 + 1] = v.y;
        xs[r][k4 * 4 + 2] = v.z; xs[r][k4 * 4 + 3] = v.w;
    }
    __syncthreads();

    int tx = tid & 15, ty = tid >> 4;
    float acc[8][4];
#pragma unroll
    for (int i = 0; i < 8; i++)
#pragma unroll
        for (int j = 0; j < 4; j++) acc[i][j] = 0.f;

#pragma unroll 8
    for (int k = 0; k < 64; k++) {
        float a[8];
#pragma unroll
        for (int i = 0; i < 8; i++) a[i] = xs[ty * 8 + i][k];
        float4 b = *(const float4*)&ws[k][tx * 4];
#pragma unroll
        for (int i = 0; i < 8; i++) {
            acc[i][0] = fmaf(a[i], b.x, acc[i][0]);
            acc[i][1] = fmaf(a[i], b.y, acc[i][1]);
            acc[i][2] = fmaf(a[i], b.z, acc[i][2]);
            acc[i][3] = fmaf(a[i], b.w, acc[i][3]);
        }
    }

    // scale by dinv[row], convert fp16, store (cols tx*4..tx*4+3 = one uint2)
#pragma unroll
    for (int i = 0; i < 8; i++) {
        int gr = row0 + ty * 8 + i;
        if (gr < NN) {
            float dv = __ldg(&g_dinv[gr]);
            union { __half2 h[2]; uint2 u; } pk;
            pk.h[0] = __floats2half2_rn(acc[i][0] * dv, acc[i][1] * dv);
            pk.h[1] = __floats2half2_rn(acc[i][2] * dv, acc[i][3] * dv);
            ((uint2*)g_t16)[gr * 16 + tx] = pk.u;
        }
    }
}

// ---------------- aggregation: warp per node, CSR gather-reduce ------------
// out[n] = relu( dinv[n] * (t16[n] + sum_{src} t16[src]) + bias )
// FC=0: -> g_h.  FC=1: fused FC(64->16) + log_softmax -> out.
template <int FC>
__global__ void k_agg(const float* __restrict__ bias,
                      const float* __restrict__ Wfc,
                      const float* __restrict__ bfc,
                      float* __restrict__ out) {
    int n    = (blockIdx.x * blockDim.x + threadIdx.x) >> 5;
    int lane = threadIdx.x & 31;
    if (n >= NN) return;
    const __half2* T16 = (const __half2*)g_t16;

    float2 sv = __half22float2(__ldg(&T16[n * 32 + lane]));
    float a0 = sv.x, a1 = sv.y;                 // self term (t16 already * dinv)

    int j = g_rowptr[n], end = g_rowptr[n + 1];
    for (; j + 16 <= end; j += 16) {
        int src[16];
#pragma unroll
        for (int q = 0; q < 16; q++) src[q] = __ldg(&g_srcs[j + q]);
        float2 v[16];
#pragma unroll
        for (int q = 0; q < 16; q++)
            v[q] = __half22float2(__ldg(&T16[src[q] * 32 + lane]));
#pragma unroll
        for (int q = 0; q < 16; q++) { a0 += v[q].x; a1 += v[q].y; }
    }
    for (; j + 4 <= end; j += 4) {
        int src[4];
#pragma unroll
        for (int q = 0; q < 4; q++) src[q] = __ldg(&g_srcs[j + q]);
        float2 v[4];
#pragma unroll
        for (int q = 0; q < 4; q++)
            v[q] = __half22float2(__ldg(&T16[src[q] * 32 + lane]));
#pragma unroll
        for (int q = 0; q < 4; q++) { a0 += v[q].x; a1 += v[q].y; }
    }
    for (; j < end; j++) {
        float2 v = __half22float2(__ldg(&T16[__ldg(&g_srcs[j]) * 32 + lane]));
        a0 += v.x; a1 += v.y;
    }

    float dn = __ldg(&g_dinv[n]);
    float2 b = __ldg(&((const float2*)bias)[lane]);
    a0 = fmaxf(fmaf(a0, dn, b.x), 0.f);
    a1 = fmaxf(fmaf(a1, dn, b.y), 0.f);

    if (FC == 0) {
        ((float2*)g_h)[n * 32 + lane] = make_float2(a0, a1);
    } else {
        // fused FC: channels (2*lane, 2*lane+1) x Wfc[64][16]
        const float4* W4 = (const float4*)Wfc;
        float p[16];
#pragma unroll
        for (int q = 0; q < 4; q++) {
            float4 w0 = __ldg(&W4[(2 * lane) * 4 + q]);
            float4 w1 = __ldg(&W4[(2 * lane + 1) * 4 + q]);
            p[4 * q + 0] = a0 * w0.x + a1 * w1.x;
            p[4 * q + 1] = a0 * w0.y + a1 * w1.y;
            p[4 * q + 2] = a0 * w0.z + a1 * w1.z;
            p[4 * q + 3] = a0 * w0.w + a1 * w1.w;
        }
#pragma unroll
        for (int off = 16; off >= 1; off >>= 1)
#pragma unroll
            for (int c = 0; c < 16; c++)
                p[c] += __shfl_xor_sync(0xffffffffu, p[c], off);

        float m = -3.4e38f;
#pragma unroll
        for (int c = 0; c < 16; c++) { p[c] += __ldg(&bfc[c]); m = fmaxf(m, p[c]); }

        float val = 0.f;
#pragma unroll
        for (int c = 0; c < 16; c++) if (lane == c) val = p[c];
        float ex = (lane < 16) ? expf(val - m) : 0.f;
#pragma unroll
        for (int off = 8; off >= 1; off >>= 1)
            ex += __shfl_xor_sync(0xffffffffu, ex, off);
        float lse = m + logf(ex);

        if (lane < 16) out[n * 16 + lane] = val - lse;
    }
}

// ---------------- launch ----------------------------------------------------
extern "C" void kernel_launch(void* const* d_in, const int* in_sizes, int n_in,
                              void* d_out, int out_size) {
    const float* x    = (const float*)d_in[0];
    const int*   ei32 = (const int*)d_in[1];   // int32 or int64 — detected on device
    const float* W1   = (const float*)d_in[2];
    const float* b1   = (const float*)d_in[3];
    const float* W2   = (const float*)d_in[4];
    const float* b2   = (const float*)d_in[5];
    const float* Wfc  = (const float*)d_in[6];
    const float* bfc  = (const float*)d_in[7];
    float*       out  = (float*)d_out;

    k_hist<<<1024, 256>>>(ei32);
    k_scanA<<<(NN + 1023) / 1024, 1024>>>();
    k_scanC<<<(NN + 255) / 256, 256>>>();
    k_scatter<<<1024, 256>>>(ei32);

    k_gemm64<<<(NN + 127) / 128, 256>>>(x, W1);   // launch #5 -> ncu target
    k_agg<0><<<(NN + 7) / 8, 256>>>(b1, nullptr, nullptr, nullptr);
    k_gemm64<<<(NN + 127) / 128, 256>>>(nullptr, W2);
    k_agg<1><<<(NN + 7) / 8, 256>>>(b2, Wfc, bfc, out);
}